// round 14
// baseline (speedup 1.0000x reference)
#include <cuda_runtime.h>
#include <math.h>

// Problem constants
#define Bsz 64
#define Lsz 24
#define Dsz 512
#define Hsz 512
#define NSLOT (Bsz*Lsz)   // 1536 node slots
#define UWLD 5120         // per-slot row: [u(2560) | w(2560)]
#define HCLD 1024         // per-slot row: [h(512) | c(512)]
#define GRID_P 128        // persistent grid (fully resident, all blocks compute)
#define NTHR_P 640        // persistent block size (20 warps, 5/SMSP)
#define FLAG_STRIDE 32    // 128B padding between flags

// dynamic smem layout for k_loop (floats): 16 K-slices of 32 k each
#define AROW 36                         // A row: 32 kk + 4 pad
#define ASLAB_STRIDE (64*AROW + 4)      // 2308 floats per A slab
#define BSLAB_STRIDE (32*40 + 4)        // 1284 floats per B slab
#define B_OFF (16*ASLAB_STRIDE)         // 36928
#define SMEM_FLOATS (16*ASLAB_STRIDE + 16*BSLAB_STRIDE)   // 57472
#define SMEM_BYTES (SMEM_FLOATS*4)      // 229888 (< 232448 limit)

typedef unsigned long long ull;

// Static scratch (no allocations allowed)
__device__ __align__(16) float g_HC[NSLOT*HCLD];   // 6.3 MB
__device__ __align__(16) float g_UW[NSLOT*UWLD];   // 31.5 MB
__device__ __align__(16) float g_NH[Bsz*Hsz];      // merged-node h, compact per batch
__device__ int   g_rowmap[Bsz];                    // slot to receive updated u/w (-1 = skip)

// Flag-based grid barrier (no atomics). Zeroed each launch by k_reset so graph
// replays stay in phase.
__device__ volatile unsigned g_flags[GRID_P*FLAG_STRIDE];

__global__ void k_reset() {
    int i = threadIdx.x;
    if (i < GRID_P) g_flags[i*FLAG_STRIDE] = 0u;
}

__device__ __forceinline__ void grid_bar(int& ep) {
    ep++;
    __syncthreads();
    if (threadIdx.x == 0) {
        __threadfence();                              // release prior writes
        g_flags[blockIdx.x*FLAG_STRIDE] = (unsigned)ep;
    }
    if (threadIdx.x < GRID_P) {
        while (g_flags[threadIdx.x*FLAG_STRIDE] < (unsigned)ep) { }
    }
    __syncthreads();
    // cross-SM data is read via __ldcg (L2) after this point -> coherent.
}

// ---- packed fp32x2 FMA (Blackwell FFMA2; bitwise == 2x scalar FFMA) --------
__device__ __forceinline__ ull pack2(float x, float y) {
    ull r; asm("mov.b64 %0, {%1, %2};" : "=l"(r) : "f"(x), "f"(y)); return r;
}
__device__ __forceinline__ void fma2(ull& d, ull a, ull b) {
    asm("fma.rn.f32x2 %0, %1, %2, %0;" : "+l"(d) : "l"(a), "l"(b));
}
__device__ __forceinline__ float2 unpack2(ull v) {
    float2 p; asm("mov.b64 {%0, %1}, %2;" : "=f"(p.x), "=f"(p.y) : "l"(v)); return p;
}

__device__ __forceinline__ float sigf(float x) { return 1.0f/(1.0f+expf(-x)); }

// Gate math for pair (slot l, slot r) at hidden dim t. v = u_l + w_r
// (comp_b folded into u). UW read via __ldcg: rows are rewritten by other SMs
// within the persistent kernel (L1 not coherent). HC slots are only ever
// written by this batch's own block (or a prior launch) -> plain loads OK.
__device__ __forceinline__ void pair_gates(int l, int r, int t, float& nh, float& nc) {
    const float* u = g_UW + (size_t)l*UWLD;
    const float* w = g_UW + (size_t)r*UWLD + 2560;
    float gi  = __ldcg(u + t)        + __ldcg(w + t);
    float gfl = __ldcg(u + 512 + t)  + __ldcg(w + 512 + t);
    float gfr = __ldcg(u + 1024 + t) + __ldcg(w + 1024 + t);
    float gu  = __ldcg(u + 1536 + t) + __ldcg(w + 1536 + t);
    float go  = __ldcg(u + 2048 + t) + __ldcg(w + 2048 + t);
    float cl  = g_HC[(size_t)l*HCLD + 512 + t];
    float cr  = g_HC[(size_t)r*HCLD + 512 + t];
    nc = cl*sigf(gfl + 1.0f) + cr*sigf(gfr + 1.0f) + tanhf(gu)*sigf(gi);
    nh = sigf(go)*tanhf(nc);
}

// ---------------------------------------------------------------------------
// NT GEMM, 128x128 tile, 8x8 microtile, FFMA2, double-buffered smem with
// register-staged prefetch (preamble only).
// ---------------------------------------------------------------------------
template<bool DUAL>
__global__ void __launch_bounds__(256, 2)
gemm128(const float* __restrict__ A, int lda,
        const float* __restrict__ Bm, int ldb,
        const float* __restrict__ bias,
        float* __restrict__ C, int ldc, int K)
{
    __shared__ __align__(16) float As[2][16][128];
    __shared__ __align__(16) float Bs[2][16][128];
    const int tid = threadIdx.x;
    const int m0 = blockIdx.y * 128;
    const int n0 = blockIdx.x * 128;
    const int tx = tid & 15;        // 8 n each
    const int ty = tid >> 4;        // 8 m each
    ull acc[8][4] = {};

    const int am_[2] = { tid >> 2, (tid + 256) >> 2 };
    const int ak_[2] = { tid & 3,  (tid + 256) & 3 };
    float4 ra[2], rb[2];

    auto ldg_chunk = [&](int k0) {
        #pragma unroll
        for (int v = 0; v < 2; v++) {
            ra[v] = *(const float4*)(A + (size_t)(m0 + am_[v])*lda + k0 + ak_[v]*4);
            int gn = n0 + am_[v];
            const float* bp;
            if (DUAL)
                bp = (gn < 2560) ? (Bm + (size_t)gn*1024 + k0 + ak_[v]*4)
                                 : (Bm + (size_t)(gn-2560)*1024 + 512 + k0 + ak_[v]*4);
            else
                bp = Bm + (size_t)gn*ldb + k0 + ak_[v]*4;
            rb[v] = *(const float4*)bp;
        }
    };
    auto sts_chunk = [&](int buf) {
        #pragma unroll
        for (int v = 0; v < 2; v++) {
            As[buf][ak_[v]*4+0][am_[v]] = ra[v].x;
            As[buf][ak_[v]*4+1][am_[v]] = ra[v].y;
            As[buf][ak_[v]*4+2][am_[v]] = ra[v].z;
            As[buf][ak_[v]*4+3][am_[v]] = ra[v].w;
            Bs[buf][ak_[v]*4+0][am_[v]] = rb[v].x;
            Bs[buf][ak_[v]*4+1][am_[v]] = rb[v].y;
            Bs[buf][ak_[v]*4+2][am_[v]] = rb[v].z;
            Bs[buf][ak_[v]*4+3][am_[v]] = rb[v].w;
        }
    };

    const int NC = K / 16;
    ldg_chunk(0);
    sts_chunk(0);
    __syncthreads();

    #pragma unroll 1
    for (int c = 0; c < NC; c++) {
        int cur = c & 1;
        if (c + 1 < NC) ldg_chunk((c + 1) * 16);
        #pragma unroll
        for (int k = 0; k < 16; k++) {
            float4 a0 = *(const float4*)&As[cur][k][ty*8];
            float4 a1 = *(const float4*)&As[cur][k][ty*8+4];
            ull am[8];
            am[0]=pack2(a0.x,a0.x); am[1]=pack2(a0.y,a0.y);
            am[2]=pack2(a0.z,a0.z); am[3]=pack2(a0.w,a0.w);
            am[4]=pack2(a1.x,a1.x); am[5]=pack2(a1.y,a1.y);
            am[6]=pack2(a1.z,a1.z); am[7]=pack2(a1.w,a1.w);
            ulonglong2 bb0 = *(const ulonglong2*)&Bs[cur][k][tx*8];
            ulonglong2 bb1 = *(const ulonglong2*)&Bs[cur][k][tx*8+4];
            ull bn_[4] = { bb0.x, bb0.y, bb1.x, bb1.y };
            #pragma unroll
            for (int i = 0; i < 8; i++)
                #pragma unroll
                for (int j = 0; j < 4; j++)
                    fma2(acc[i][j], am[i], bn_[j]);
        }
        if (c + 1 < NC) {
            __syncthreads();
            sts_chunk(cur ^ 1);
            __syncthreads();
        }
    }

    #pragma unroll
    for (int i = 0; i < 8; i++) {
        int m = m0 + ty*8 + i;
        #pragma unroll
        for (int q = 0; q < 2; q++) {
            int gn = n0 + tx*8 + q*4;
            float b0=0.f,b1=0.f,b2=0.f,b3=0.f;
            if (bias && (!DUAL || gn < 2560)) {
                b0 = bias[gn]; b1 = bias[gn+1]; b2 = bias[gn+2]; b3 = bias[gn+3];
            }
            float2 p0 = unpack2(acc[i][q*2]);
            float2 p1 = unpack2(acc[i][q*2+1]);
            float4 o;
            o.x = p0.x + b0; o.y = p0.y + b1;
            o.z = p1.x + b2; o.w = p1.y + b3;
            *(float4*)(C + (size_t)m*ldc + gn) = o;
        }
    }
}

// ---------------------------------------------------------------------------
// Update-GEMM phase: UW[rowmap[m]] <- u|w projection of g_NH[m].
// 128 blocks x 64x40 tiles. 640 threads: 16-way split-K (s = tid&15, 32 k
// each) x 40 positions (pos = tid>>4) of 8m x 8n microtiles. B resident in
// smem across all 22 iterations. 3-stage deterministic epilogue.
__device__ void gemm_update_phase(int bid, const float* __restrict__ comp_b,
                                  int* s_rm, float* sA, float* sB)
{
    const int tid = threadIdx.x;
    if (tid < Bsz) s_rm[tid] = __ldcg(&g_rowmap[tid]);
    // stage A: g_NH [64 m][512 k] -> sA[s][m][kk0..31]
    #pragma unroll
    for (int v = 0; v < 13; v++) {
        int idx = tid + v*NTHR_P;
        if (idx < 8192) {
            int m = idx >> 7, kq = idx & 127;
            float4 a = __ldcg((const float4*)(g_NH + m*512 + kq*4));
            int s = kq >> 3, kk = (kq & 7)*4;
            *(float4*)&sA[s*ASLAB_STRIDE + m*AROW + kk] = a;
        }
    }
    __syncthreads();

    const int s   = tid & 15;          // K-slice 0..15 (k = s*32 .. s*32+31)
    const int pos = tid >> 4;          // 0..39
    const int ty  = pos / 5;           // m group (8 rows each)
    const int tx  = pos - ty*5;        // n group (8 cols each)
    const float* aBase = sA + s*ASLAB_STRIDE + (ty*8)*AROW;
    const float* bBase = sB + s*BSLAB_STRIDE + tx*8;
    ull acc[8][4];
    #pragma unroll
    for (int i = 0; i < 8; i++) { acc[i][0]=0; acc[i][1]=0; acc[i][2]=0; acc[i][3]=0; }

    #pragma unroll 8
    for (int kk = 0; kk < 32; kk++) {
        ulonglong2 b01 = *(const ulonglong2*)(bBase + kk*40);
        ulonglong2 b23 = *(const ulonglong2*)(bBase + kk*40 + 4);
        #pragma unroll
        for (int i = 0; i < 8; i++) {
            float av = aBase[i*AROW + kk];
            ull am = pack2(av, av);
            fma2(acc[i][0], am, b01.x);
            fma2(acc[i][1], am, b01.y);
            fma2(acc[i][2], am, b23.x);
            fma2(acc[i][3], am, b23.y);
        }
    }

    // 3-stage epilogue (deterministic order): scratch reuses sA.
    // slot(pos,i,s8) = 8 floats at ((pos*8+i)*8 + s8)*8, s8 = s&7. 80 KB.
    __syncthreads();                       // all kk reads of sA done
    float* scratch = sA;
    if (s < 8) {                           // stage 1: low slices write
        #pragma unroll
        for (int i = 0; i < 8; i++) {
            float4* dst = (float4*)&scratch[(((pos*8 + i)*8) + s)*8];
            float2 p0 = unpack2(acc[i][0]), p1 = unpack2(acc[i][1]);
            float2 p2 = unpack2(acc[i][2]), p3 = unpack2(acc[i][3]);
            dst[0] = make_float4(p0.x, p0.y, p1.x, p1.y);
            dst[1] = make_float4(p2.x, p2.y, p3.x, p3.y);
        }
    }
    __syncthreads();
    if (s >= 8) {                          // stage 2: high slices accumulate
        #pragma unroll
        for (int i = 0; i < 8; i++) {
            float4* dst = (float4*)&scratch[(((pos*8 + i)*8) + (s-8))*8];
            float2 p0 = unpack2(acc[i][0]), p1 = unpack2(acc[i][1]);
            float2 p2 = unpack2(acc[i][2]), p3 = unpack2(acc[i][3]);
            float4 v0 = dst[0], v1 = dst[1];
            dst[0] = make_float4(v0.x+p0.x, v0.y+p0.y, v0.z+p1.x, v0.w+p1.y);
            dst[1] = make_float4(v1.x+p2.x, v1.y+p2.y, v1.z+p3.x, v1.w+p3.y);
        }
    }
    __syncthreads();
    if (tid < 320) {                       // stage 3: 1 output group / thread
        int m2  = tid / 5;                 // 0..63
        int tx2 = tid - m2*5;              // 0..4
        int pos2 = (m2 >> 3)*5 + tx2;
        int i2   = m2 & 7;
        float c[8];
        #pragma unroll
        for (int j = 0; j < 8; j++) c[j] = 0.f;
        #pragma unroll
        for (int s2 = 0; s2 < 8; s2++) {   // fixed order -> deterministic
            const float4* src = (const float4*)&scratch[(((pos2*8 + i2)*8) + s2)*8];
            float4 v0 = src[0], v1 = src[1];
            c[0]+=v0.x; c[1]+=v0.y; c[2]+=v0.z; c[3]+=v0.w;
            c[4]+=v1.x; c[5]+=v1.y; c[6]+=v1.z; c[7]+=v1.w;
        }
        int orow = s_rm[m2];
        if (orow >= 0) {
            int gn = bid*40 + tx2*8;
            if (gn < 2560) {               // block-uniform (2560 % 40 == 0)
                #pragma unroll
                for (int j = 0; j < 8; j++) c[j] += comp_b[gn + j];
            }
            float4 o0, o1;
            o0.x=c[0]; o0.y=c[1]; o0.z=c[2]; o0.w=c[3];
            o1.x=c[4]; o1.y=c[5]; o1.z=c[6]; o1.w=c[7];
            *(float4*)(g_UW + (size_t)orow*UWLD + gn)     = o0;
            *(float4*)(g_UW + (size_t)orow*UWLD + gn + 4) = o1;
        }
    }
    __syncthreads();                       // scratch (sA) free for next phase
}

// ---------------------------------------------------------------------------
// Persistent loop: iter-0 scoring + 23 step phases + 22 update-GEMM phases.
// Blocks 0..63 own batch b's tree state; all 128 blocks do the update GEMM.
__global__ void __launch_bounds__(NTHR_P, 1)
k_loop(const float* __restrict__ q, const int* __restrict__ length,
       float* __restrict__ out,
       const float* __restrict__ comp_W, const float* __restrict__ comp_b)
{
    extern __shared__ float sdyn[];
    float* sA = sdyn;
    float* sB = sdyn + B_OFF;
    const int bid = blockIdx.x;
    const int tid = threadIdx.x;
    int ep = 0;
    __shared__ int   s_pos[Lsz];
    __shared__ float s_sc[Lsz];
    __shared__ float red[2][4];
    __shared__ int   s_k, s_len;
    __shared__ int   s_rm[Bsz];
    const bool stepB = (bid < Bsz);
    const int b = bid;

    // preload this block's comp_W slice (40 virtual rows x 512 k) into sB
    // as 16 [kk 0..31][40 n] slabs; persists across all iterations.
    for (int idx = tid; idx < 5120; idx += NTHR_P) {
        int kq = idx / 40;                 // 0..127 (float4 index along k)
        int n  = idx - kq*40;
        int gn = bid*40 + n;
        int gk = kq*4;
        const float* bp = (gn < 2560)
            ? (comp_W + (size_t)gn*1024 + gk)
            : (comp_W + (size_t)(gn-2560)*1024 + 512 + gk);
        float4 bv = *(const float4*)bp;
        int s = gk >> 5, kk = gk & 31;
        float* dst = &sB[s*BSLAB_STRIDE + kk*40 + n];
        dst[0] = bv.x; dst[40] = bv.y; dst[80] = bv.z; dst[120] = bv.w;
    }

    if (stepB) {
        if (tid == 0) { s_len = length[b]; s_k = -1; }
        if (tid < Lsz) s_pos[tid] = b*Lsz + tid;
        // iteration-0 scoring: all 23 adjacent pairs, one warp per pair
        int w = tid >> 5, lane = tid & 31;
        for (int j = w; j < Lsz-1; j += 20) {
            int l = b*Lsz + j, r = l + 1;
            float part = 0.f;
            #pragma unroll
            for (int sdim = 0; sdim < 16; sdim++) {
                int t = lane + 32*sdim;
                float nh, nc; pair_gates(l, r, t, nh, nc);
                part += nh * q[t];
            }
            #pragma unroll
            for (int o = 16; o; o >>= 1) part += __shfl_down_sync(0xffffffffu, part, o);
            if (lane == 0) s_sc[j] = part;
        }
    }
    __syncthreads();

    for (int iter = 0; iter < Lsz-1; iter++) {
        if (stepB) {
            int nvalid = s_len - 1 - iter;
            if (iter > 0 && s_k >= 0) {
                int kp = s_k;                       // rescore pairs kp-1, kp
                int half = 0, ht = 0, jj = -1;
                bool act = false;
                float part = 0.f;
                if (tid < 256) {
                    half = tid >> 7;
                    ht   = tid & 127;
                    jj = kp - 1 + half;
                    act = (jj >= 0) && (jj < nvalid);
                    if (act) {
                        int l = s_pos[jj], r = s_pos[jj+1];
                        #pragma unroll
                        for (int sdim = 0; sdim < 4; sdim++) {
                            int t = ht + sdim*128;
                            float nh, nc; pair_gates(l, r, t, nh, nc);
                            part += nh * q[t];
                        }
                    }
                    #pragma unroll
                    for (int o = 16; o; o >>= 1) part += __shfl_down_sync(0xffffffffu, part, o);
                    if ((ht & 31) == 0) red[half][ht >> 5] = part;
                }
                __syncthreads();
                if (tid < 256 && (tid & 127) == 0 && act)
                    s_sc[jj] = red[half][0] + red[half][1] + red[half][2] + red[half][3];
                __syncthreads();
            }
            // argmax with first-index tie-break (matches jnp.argmax)
            if (tid < 32) {
                float v = (tid < nvalid) ? s_sc[tid] : -1e9f;
                int idx = tid;
                #pragma unroll
                for (int o = 16; o; o >>= 1) {
                    float v2 = __shfl_down_sync(0xffffffffu, v, o);
                    int  i2  = __shfl_down_sync(0xffffffffu, idx, o);
                    if (v2 > v || (v2 == v && i2 < idx)) { v = v2; idx = i2; }
                }
                if (tid == 0) s_k = (nvalid > 0) ? idx : -1;
            }
            __syncthreads();
            int k = s_k;
            if (k >= 0) {
                int l = s_pos[k], r = s_pos[k+1];
                for (int t = tid; t < 512; t += NTHR_P) {
                    float nh, nc; pair_gates(l, r, t, nh, nc);
                    g_HC[(size_t)l*HCLD + t]       = nh;   // merged node reuses left slot
                    g_HC[(size_t)l*HCLD + 512 + t] = nc;
                    g_NH[b*512 + t] = nh;                  // staged for update GEMM
                }
                __syncthreads();
                if (tid == 0) {
                    g_rowmap[b] = l;
                    for (int j = k+1; j < Lsz-1; j++) {    // shift logical lists
                        s_pos[j] = s_pos[j+1];
                        s_sc[j]  = s_sc[j+1];
                    }
                }
            } else {
                if (tid == 0) g_rowmap[b] = -1;            // frozen batch
            }
        }
        grid_bar(ep);
        if (iter < Lsz-2) {
            gemm_update_phase(bid, comp_b, s_rm, sA, sB);
            grid_bar(ep);
        }
    }

    if (stepB) {
        int slot = s_pos[0];
        for (int t = tid; t < 512; t += NTHR_P)
            out[b*512 + t] = g_HC[(size_t)slot*HCLD + t];
    }
}

// ---------------------------------------------------------------------------
extern "C" void kernel_launch(void* const* d_in, const int* in_sizes, int n_in,
                              void* d_out, int out_size) {
    const float* inp    = (const float*)d_in[0];
    const int*   length = (const int*)  d_in[1];
    const float* word_W = (const float*)d_in[2];
    const float* word_b = (const float*)d_in[3];
    const float* comp_W = (const float*)d_in[4];
    const float* comp_b = (const float*)d_in[5];
    const float* q      = (const float*)d_in[6];
    float* out = (float*)d_out;
    (void)in_sizes; (void)n_in; (void)out_size;

    float *HC = nullptr, *UW = nullptr;
    cudaGetSymbolAddress((void**)&HC, g_HC);
    cudaGetSymbolAddress((void**)&UW, g_UW);

    cudaFuncSetAttribute(k_loop, cudaFuncAttributeMaxDynamicSharedMemorySize,
                         SMEM_BYTES);

    k_reset<<<1, 128>>>();

    // hc = inp @ word_W.T + word_b  -> HC[slot][h|c]
    gemm128<false><<<dim3(1024/128, NSLOT/128), 256>>>(
        inp, Dsz, word_W, Dsz, word_b, HC, HCLD, Dsz);

    // u|w projections for all 1536 leaf nodes (comp_b folded into u half)
    gemm128<true><<<dim3(5120/128, NSLOT/128), 256>>>(
        HC, HCLD, comp_W, 0, comp_b, UW, UWLD, Hsz);

    // persistent loop: iter-0 scoring + 23 merges + 22 incremental u/w updates
    k_loop<<<GRID_P, NTHR_P, SMEM_BYTES>>>(q, length, out, comp_W, comp_b);
}

// round 15
// speedup vs baseline: 1.1647x; 1.1647x over previous
#include <cuda_runtime.h>
#include <math.h>

// Problem constants
#define Bsz 64
#define Lsz 24
#define Dsz 512
#define Hsz 512
#define NSLOT (Bsz*Lsz)   // 1536 node slots
#define UWLD 5120         // per-slot row: [u(2560) | w(2560)]
#define HCLD 1024         // per-slot row: [h(512) | c(512)]
#define GRID_P 128        // persistent grid (fully resident, all blocks compute)
#define NTHR_P 320        // persistent block size (10 warps)  [R13 structure]
#define FLAG_STRIDE 32    // 128B padding between flags

// dynamic smem layout for k_loop (floats) — R13 layout
#define AROW 68                         // A row pad (64 + 4)
#define ASLAB_STRIDE (64*AROW + 4)      // 4356, +4 stagger per K-slice slab
#define BSLAB_STRIDE (64*40 + 4)        // 2564
#define B_OFF (8*ASLAB_STRIDE)          // 34848
#define SMEM_FLOATS (8*ASLAB_STRIDE + 8*BSLAB_STRIDE)   // 55360
#define SMEM_BYTES (SMEM_FLOATS*4)      // 221440

typedef unsigned long long ull;

// Static scratch (no allocations allowed)
__device__ __align__(16) float g_HC[NSLOT*HCLD];   // 6.3 MB
__device__ __align__(16) float g_UW[NSLOT*UWLD];   // 31.5 MB
__device__ __align__(16) float g_NH[Bsz*Hsz];      // merged-node h, by sorted rank
__device__ int   g_rowmap[Bsz];                    // per-rank slot for u/w update (-1 = skip)

// Flag-based grid barrier (no atomics). Zeroed each launch by k_reset so graph
// replays stay in phase.
__device__ volatile unsigned g_flags[GRID_P*FLAG_STRIDE];

__global__ void k_reset() {
    int i = threadIdx.x;
    if (i < GRID_P) g_flags[i*FLAG_STRIDE] = 0u;
}

__device__ __forceinline__ void grid_bar(int& ep) {
    ep++;
    __syncthreads();
    if (threadIdx.x == 0) {
        __threadfence();                              // release prior writes
        g_flags[blockIdx.x*FLAG_STRIDE] = (unsigned)ep;
    }
    if (threadIdx.x < GRID_P) {
        while (g_flags[threadIdx.x*FLAG_STRIDE] < (unsigned)ep) { }
    }
    __syncthreads();
    // cross-SM data is read via __ldcg (L2) after this point -> coherent.
}

// ---- packed fp32x2 FMA (Blackwell FFMA2; bitwise == 2x scalar FFMA) --------
__device__ __forceinline__ ull pack2(float x, float y) {
    ull r; asm("mov.b64 %0, {%1, %2};" : "=l"(r) : "f"(x), "f"(y)); return r;
}
__device__ __forceinline__ void fma2(ull& d, ull a, ull b) {
    asm("fma.rn.f32x2 %0, %1, %2, %0;" : "+l"(d) : "l"(a), "l"(b));
}
__device__ __forceinline__ float2 unpack2(ull v) {
    float2 p; asm("mov.b64 {%0, %1}, %2;" : "=f"(p.x), "=f"(p.y) : "l"(v)); return p;
}

__device__ __forceinline__ float sigf(float x) { return 1.0f/(1.0f+expf(-x)); }

// Gate math for pair (slot l, slot r) at hidden dim t. v = u_l + w_r
// (comp_b folded into u). UW read via __ldcg (cross-SM written within launch).
__device__ __forceinline__ void pair_gates(int l, int r, int t, float& nh, float& nc) {
    const float* u = g_UW + (size_t)l*UWLD;
    const float* w = g_UW + (size_t)r*UWLD + 2560;
    float gi  = __ldcg(u + t)        + __ldcg(w + t);
    float gfl = __ldcg(u + 512 + t)  + __ldcg(w + 512 + t);
    float gfr = __ldcg(u + 1024 + t) + __ldcg(w + 1024 + t);
    float gu  = __ldcg(u + 1536 + t) + __ldcg(w + 1536 + t);
    float go  = __ldcg(u + 2048 + t) + __ldcg(w + 2048 + t);
    float cl  = g_HC[(size_t)l*HCLD + 512 + t];
    float cr  = g_HC[(size_t)r*HCLD + 512 + t];
    nc = cl*sigf(gfl + 1.0f) + cr*sigf(gfr + 1.0f) + tanhf(gu)*sigf(gi);
    nh = sigf(go)*tanhf(nc);
}

// ---------------------------------------------------------------------------
// NT GEMM, 128x128 tile, 8x8 microtile, FFMA2, double-buffered smem with
// register-staged prefetch (preamble only). Unchanged from R13.
// ---------------------------------------------------------------------------
template<bool DUAL>
__global__ void __launch_bounds__(256, 2)
gemm128(const float* __restrict__ A, int lda,
        const float* __restrict__ Bm, int ldb,
        const float* __restrict__ bias,
        float* __restrict__ C, int ldc, int K)
{
    __shared__ __align__(16) float As[2][16][128];
    __shared__ __align__(16) float Bs[2][16][128];
    const int tid = threadIdx.x;
    const int m0 = blockIdx.y * 128;
    const int n0 = blockIdx.x * 128;
    const int tx = tid & 15;
    const int ty = tid >> 4;
    ull acc[8][4] = {};

    const int am_[2] = { tid >> 2, (tid + 256) >> 2 };
    const int ak_[2] = { tid & 3,  (tid + 256) & 3 };
    float4 ra[2], rb[2];

    auto ldg_chunk = [&](int k0) {
        #pragma unroll
        for (int v = 0; v < 2; v++) {
            ra[v] = *(const float4*)(A + (size_t)(m0 + am_[v])*lda + k0 + ak_[v]*4);
            int gn = n0 + am_[v];
            const float* bp;
            if (DUAL)
                bp = (gn < 2560) ? (Bm + (size_t)gn*1024 + k0 + ak_[v]*4)
                                 : (Bm + (size_t)(gn-2560)*1024 + 512 + k0 + ak_[v]*4);
            else
                bp = Bm + (size_t)gn*ldb + k0 + ak_[v]*4;
            rb[v] = *(const float4*)bp;
        }
    };
    auto sts_chunk = [&](int buf) {
        #pragma unroll
        for (int v = 0; v < 2; v++) {
            As[buf][ak_[v]*4+0][am_[v]] = ra[v].x;
            As[buf][ak_[v]*4+1][am_[v]] = ra[v].y;
            As[buf][ak_[v]*4+2][am_[v]] = ra[v].z;
            As[buf][ak_[v]*4+3][am_[v]] = ra[v].w;
            Bs[buf][ak_[v]*4+0][am_[v]] = rb[v].x;
            Bs[buf][ak_[v]*4+1][am_[v]] = rb[v].y;
            Bs[buf][ak_[v]*4+2][am_[v]] = rb[v].z;
            Bs[buf][ak_[v]*4+3][am_[v]] = rb[v].w;
        }
    };

    const int NC = K / 16;
    ldg_chunk(0);
    sts_chunk(0);
    __syncthreads();

    #pragma unroll 1
    for (int c = 0; c < NC; c++) {
        int cur = c & 1;
        if (c + 1 < NC) ldg_chunk((c + 1) * 16);
        #pragma unroll
        for (int k = 0; k < 16; k++) {
            float4 a0 = *(const float4*)&As[cur][k][ty*8];
            float4 a1 = *(const float4*)&As[cur][k][ty*8+4];
            ull am[8];
            am[0]=pack2(a0.x,a0.x); am[1]=pack2(a0.y,a0.y);
            am[2]=pack2(a0.z,a0.z); am[3]=pack2(a0.w,a0.w);
            am[4]=pack2(a1.x,a1.x); am[5]=pack2(a1.y,a1.y);
            am[6]=pack2(a1.z,a1.z); am[7]=pack2(a1.w,a1.w);
            ulonglong2 bb0 = *(const ulonglong2*)&Bs[cur][k][tx*8];
            ulonglong2 bb1 = *(const ulonglong2*)&Bs[cur][k][tx*8+4];
            ull bn_[4] = { bb0.x, bb0.y, bb1.x, bb1.y };
            #pragma unroll
            for (int i = 0; i < 8; i++)
                #pragma unroll
                for (int j = 0; j < 4; j++)
                    fma2(acc[i][j], am[i], bn_[j]);
        }
        if (c + 1 < NC) {
            __syncthreads();
            sts_chunk(cur ^ 1);
            __syncthreads();
        }
    }

    #pragma unroll
    for (int i = 0; i < 8; i++) {
        int m = m0 + ty*8 + i;
        #pragma unroll
        for (int q = 0; q < 2; q++) {
            int gn = n0 + tx*8 + q*4;
            float b0=0.f,b1=0.f,b2=0.f,b3=0.f;
            if (bias && (!DUAL || gn < 2560)) {
                b0 = bias[gn]; b1 = bias[gn+1]; b2 = bias[gn+2]; b3 = bias[gn+3];
            }
            float2 p0 = unpack2(acc[i][q*2]);
            float2 p1 = unpack2(acc[i][q*2+1]);
            float4 o;
            o.x = p0.x + b0; o.y = p0.y + b1;
            o.z = p1.x + b2; o.w = p1.y + b3;
            *(float4*)(C + (size_t)m*ldc + gn) = o;
        }
    }
}

// ---------------------------------------------------------------------------
// Update-GEMM phase (R13 structure, 320 threads, 8-way split-K) with:
//  - act-based prefix skipping (rows >= act are frozen; whole ty-groups skip)
//  - vectorized A reads (LDS.128 along kk, 4 kk per step; same accum order)
__device__ void gemm_update_phase(int bid, const float* __restrict__ comp_b,
                                  int* s_rm, float* sA, float* sB, int act)
{
    const int tid = threadIdx.x;
    if (tid < Bsz) s_rm[tid] = __ldcg(&g_rowmap[tid]);
    // stage A: g_NH [64 m][512 k] -> sA[s][m][kk0..63]
    #pragma unroll
    for (int v = 0; v < 26; v++) {
        int idx = tid + v*NTHR_P;
        if (idx < 8192) {
            int m = idx >> 7, kq = idx & 127;
            float4 a = __ldcg((const float4*)(g_NH + m*512 + kq*4));
            int s = kq >> 4, kk = (kq & 15)*4;
            *(float4*)&sA[s*ASLAB_STRIDE + m*AROW + kk] = a;
        }
    }
    __syncthreads();

    const int s   = tid & 7;           // K-slice 0..7 (k = s*64 .. s*64+63)
    const int pos = tid >> 3;          // 0..39
    const int ty  = pos / 5;           // m group (8 rows each)
    const int tx  = pos - ty*5;        // n group (8 cols each)
    const float* aBase = sA + s*ASLAB_STRIDE + (ty*8)*AROW;
    const float* bBase = sB + s*BSLAB_STRIDE + tx*8;
    const bool active = (ty*8 < act);  // sorted ranks: frozen rows are a suffix
    ull acc[8][4];
    #pragma unroll
    for (int i = 0; i < 8; i++) { acc[i][0]=0; acc[i][1]=0; acc[i][2]=0; acc[i][3]=0; }

    if (active) {
        #pragma unroll 2
        for (int kq = 0; kq < 16; kq++) {
            float4 av[8];
            #pragma unroll
            for (int i = 0; i < 8; i++)
                av[i] = *(const float4*)(aBase + i*AROW + kq*4);
            #pragma unroll
            for (int j2 = 0; j2 < 4; j2++) {
                const float* bk = bBase + (kq*4 + j2)*40;
                ulonglong2 b01 = *(const ulonglong2*)bk;
                ulonglong2 b23 = *(const ulonglong2*)(bk + 4);
                #pragma unroll
                for (int i = 0; i < 8; i++) {
                    float avf = (j2 == 0) ? av[i].x : (j2 == 1) ? av[i].y
                              : (j2 == 2) ? av[i].z : av[i].w;
                    ull am = pack2(avf, avf);
                    fma2(acc[i][0], am, b01.x);
                    fma2(acc[i][1], am, b01.y);
                    fma2(acc[i][2], am, b23.x);
                    fma2(acc[i][3], am, b23.y);
                }
            }
        }
    }

    // Epilogue: bulk scratch write + single parallel reduce (R13 form),
    // guarded by activity. scratch reuses sA.
    __syncthreads();                       // all kk reads of sA done
    float* scratch = sA;
    if (active) {
        #pragma unroll
        for (int i = 0; i < 8; i++) {
            float4* dst = (float4*)&scratch[(((pos*8 + i)*8) + s)*8];
            float2 p0 = unpack2(acc[i][0]), p1 = unpack2(acc[i][1]);
            float2 p2 = unpack2(acc[i][2]), p3 = unpack2(acc[i][3]);
            dst[0] = make_float4(p0.x, p0.y, p1.x, p1.y);
            dst[1] = make_float4(p2.x, p2.y, p3.x, p3.y);
        }
    }
    __syncthreads();
    {
        int m2  = tid / 5;                 // 0..63 (sorted rank)
        int tx2 = tid - m2*5;              // 0..4
        int orow = s_rm[m2];
        if (orow >= 0) {                   // frozen ranks skip entirely
            int pos2 = (m2 >> 3)*5 + tx2;
            int i2   = m2 & 7;
            float c[8];
            #pragma unroll
            for (int j = 0; j < 8; j++) c[j] = 0.f;
            #pragma unroll
            for (int s2 = 0; s2 < 8; s2++) {   // fixed order: deterministic
                const float4* src = (const float4*)&scratch[(((pos2*8 + i2)*8) + s2)*8];
                float4 v0 = src[0], v1 = src[1];
                c[0]+=v0.x; c[1]+=v0.y; c[2]+=v0.z; c[3]+=v0.w;
                c[4]+=v1.x; c[5]+=v1.y; c[6]+=v1.z; c[7]+=v1.w;
            }
            int gn = bid*40 + tx2*8;
            if (gn < 2560) {               // block-uniform (2560 % 40 == 0)
                #pragma unroll
                for (int j = 0; j < 8; j++) c[j] += comp_b[gn + j];
            }
            float4 o0, o1;
            o0.x=c[0]; o0.y=c[1]; o0.z=c[2]; o0.w=c[3];
            o1.x=c[4]; o1.y=c[5]; o1.z=c[6]; o1.w=c[7];
            *(float4*)(g_UW + (size_t)orow*UWLD + gn)     = o0;
            *(float4*)(g_UW + (size_t)orow*UWLD + gn + 4) = o1;
        }
    }
    __syncthreads();                       // scratch (sA) free for next phase
}

// ---------------------------------------------------------------------------
// Persistent loop: iter-0 scoring + 23 step phases + 22 update-GEMM phases.
// Batches are assigned to GEMM rows in descending-length order so frozen rows
// form a suffix (prefix skipping). Blocks 0..63 own sorted-rank bid's batch.
__global__ void __launch_bounds__(NTHR_P, 1)
k_loop(const float* __restrict__ q, const int* __restrict__ length,
       float* __restrict__ out,
       const float* __restrict__ comp_W, const float* __restrict__ comp_b)
{
    extern __shared__ float sdyn[];
    float* sA = sdyn;
    float* sB = sdyn + B_OFF;
    const int bid = blockIdx.x;
    const int tid = threadIdx.x;
    int ep = 0;
    __shared__ int   s_pos[Lsz];
    __shared__ float s_sc[Lsz];
    __shared__ float red[2][4];
    __shared__ int   s_k, s_len;
    __shared__ int   s_rm[Bsz];
    __shared__ int   s_perm[Bsz];     // sorted rank -> batch
    __shared__ int   s_act[Lsz];      // active count per iteration
    const bool stepB = (bid < Bsz);

    // deterministic desc-length sort (tie -> lower batch index first);
    // every block computes the identical permutation.
    if (tid < Bsz) {
        int myb = tid, mylen = length[myb];
        int rank = 0;
        for (int b2 = 0; b2 < Bsz; b2++) {
            int l2 = length[b2];
            if (l2 > mylen || (l2 == mylen && b2 < myb)) rank++;
        }
        s_perm[rank] = myb;
    }
    if (tid >= 64 && tid < 64 + Lsz) {
        int iter = tid - 64;
        int cnt = 0;
        for (int b2 = 0; b2 < Bsz; b2++)
            if (length[b2] - 1 > iter) cnt++;
        s_act[iter] = cnt;
    }

    // preload this block's comp_W slice (40 virtual rows x 512 k) into sB
    // as [s][kk][n] slabs; persists across all iterations.
    for (int idx = tid; idx < 5120; idx += NTHR_P) {
        int kq = idx / 40;
        int n  = idx - kq*40;
        int gn = bid*40 + n;
        int gk = kq*4;
        const float* bp = (gn < 2560)
            ? (comp_W + (size_t)gn*1024 + gk)
            : (comp_W + (size_t)(gn-2560)*1024 + 512 + gk);
        float4 bv = *(const float4*)bp;
        int s = gk >> 6, kk = gk & 63;
        float* dst = &sB[s*BSLAB_STRIDE + kk*40 + n];
        dst[0] = bv.x; dst[40] = bv.y; dst[80] = bv.z; dst[120] = bv.w;
    }
    __syncthreads();
    const int b = stepB ? s_perm[bid] : 0;   // batch owned by this rank

    if (stepB) {
        if (tid == 0) { s_len = length[b]; s_k = -1; }
        if (tid < Lsz) s_pos[tid] = b*Lsz + tid;
        // iteration-0 scoring: all 23 adjacent pairs, one warp per pair
        int w = tid >> 5, lane = tid & 31;
        for (int j = w; j < Lsz-1; j += 10) {
            int l = b*Lsz + j, r = l + 1;
            float part = 0.f;
            #pragma unroll
            for (int sdim = 0; sdim < 16; sdim++) {
                int t = lane + 32*sdim;
                float nh, nc; pair_gates(l, r, t, nh, nc);
                part += nh * q[t];
            }
            #pragma unroll
            for (int o = 16; o; o >>= 1) part += __shfl_down_sync(0xffffffffu, part, o);
            if (lane == 0) s_sc[j] = part;
        }
    }
    __syncthreads();

    for (int iter = 0; iter < Lsz-1; iter++) {
        if (stepB) {
            int nvalid = s_len - 1 - iter;
            if (iter > 0 && s_k >= 0) {
                int kp = s_k;                       // rescore pairs kp-1, kp
                int half = 0, ht = 0, jj = -1;
                bool act2 = false;
                float part = 0.f;
                if (tid < 256) {
                    half = tid >> 7;
                    ht   = tid & 127;
                    jj = kp - 1 + half;
                    act2 = (jj >= 0) && (jj < nvalid);
                    if (act2) {
                        int l = s_pos[jj], r = s_pos[jj+1];
                        #pragma unroll
                        for (int sdim = 0; sdim < 4; sdim++) {
                            int t = ht + sdim*128;
                            float nh, nc; pair_gates(l, r, t, nh, nc);
                            part += nh * q[t];
                        }
                    }
                    #pragma unroll
                    for (int o = 16; o; o >>= 1) part += __shfl_down_sync(0xffffffffu, part, o);
                    if ((ht & 31) == 0) red[half][ht >> 5] = part;
                }
                __syncthreads();
                if (tid < 256 && (tid & 127) == 0 && act2)
                    s_sc[jj] = red[half][0] + red[half][1] + red[half][2] + red[half][3];
                __syncthreads();
            }
            // argmax with first-index tie-break (matches jnp.argmax)
            if (tid < 32) {
                float v = (tid < nvalid) ? s_sc[tid] : -1e9f;
                int idx = tid;
                #pragma unroll
                for (int o = 16; o; o >>= 1) {
                    float v2 = __shfl_down_sync(0xffffffffu, v, o);
                    int  i2  = __shfl_down_sync(0xffffffffu, idx, o);
                    if (v2 > v || (v2 == v && i2 < idx)) { v = v2; idx = i2; }
                }
                if (tid == 0) s_k = (nvalid > 0) ? idx : -1;
            }
            __syncthreads();
            int k = s_k;
            if (k >= 0) {
                int l = s_pos[k], r = s_pos[k+1];
                for (int t = tid; t < 512; t += NTHR_P) {
                    float nh, nc; pair_gates(l, r, t, nh, nc);
                    g_HC[(size_t)l*HCLD + t]       = nh;   // merged node reuses left slot
                    g_HC[(size_t)l*HCLD + 512 + t] = nc;
                    g_NH[bid*512 + t] = nh;                // staged by sorted rank
                }
                __syncthreads();
                if (tid == 0) {
                    g_rowmap[bid] = l;
                    for (int j = k+1; j < Lsz-1; j++) {    // shift logical lists
                        s_pos[j] = s_pos[j+1];
                        s_sc[j]  = s_sc[j+1];
                    }
                }
            } else {
                if (tid == 0) g_rowmap[bid] = -1;          // frozen batch
            }
        }
        grid_bar(ep);
        if (iter < Lsz-2) {
            gemm_update_phase(bid, comp_b, s_rm, sA, sB, s_act[iter]);
            grid_bar(ep);
        }
    }

    if (stepB) {
        int slot = s_pos[0];
        for (int t = tid; t < 512; t += NTHR_P)
            out[b*512 + t] = g_HC[(size_t)slot*HCLD + t];
    }
}

// ---------------------------------------------------------------------------
extern "C" void kernel_launch(void* const* d_in, const int* in_sizes, int n_in,
                              void* d_out, int out_size) {
    const float* inp    = (const float*)d_in[0];
    const int*   length = (const int*)  d_in[1];
    const float* word_W = (const float*)d_in[2];
    const float* word_b = (const float*)d_in[3];
    const float* comp_W = (const float*)d_in[4];
    const float* comp_b = (const float*)d_in[5];
    const float* q      = (const float*)d_in[6];
    float* out = (float*)d_out;
    (void)in_sizes; (void)n_in; (void)out_size;

    float *HC = nullptr, *UW = nullptr;
    cudaGetSymbolAddress((void**)&HC, g_HC);
    cudaGetSymbolAddress((void**)&UW, g_UW);

    cudaFuncSetAttribute(k_loop, cudaFuncAttributeMaxDynamicSharedMemorySize,
                         SMEM_BYTES);

    k_reset<<<1, 128>>>();

    // hc = inp @ word_W.T + word_b  -> HC[slot][h|c]
    gemm128<false><<<dim3(1024/128, NSLOT/128), 256>>>(
        inp, Dsz, word_W, Dsz, word_b, HC, HCLD, Dsz);

    // u|w projections for all 1536 leaf nodes (comp_b folded into u half)
    gemm128<true><<<dim3(5120/128, NSLOT/128), 256>>>(
        HC, HCLD, comp_W, 0, comp_b, UW, UWLD, Hsz);

    // persistent loop: iter-0 scoring + 23 merges + 22 incremental u/w updates
    k_loop<<<GRID_P, NTHR_P, SMEM_BYTES>>>(q, length, out, comp_W, comp_b);
}